// round 16
// baseline (speedup 1.0000x reference)
#include <cuda_runtime.h>

#define EPSF 1e-5f
#define NB   128   // 128 blocks < 148 SMs -> co-resident; per-batch barriers over 64 blocks

// Scratch (__device__ globals per allocation-free rule)
__device__ float4 g_xy4[2 * 64 * 256];    // [b][c/2][j] = {x(c0),y(c0),x(c1),y(c1)} normalized
__device__ float2 g_s2 [2 * 64 * 256];    // [b][o/2][j] = {s(o0), s(o1)}
__device__ unsigned g_bar2[2] = {0, 0};
__device__ volatile unsigned g_gen2[2] = {0, 0};

// ---- packed f32x2 helpers ----
__device__ __forceinline__ unsigned long long dup2(float a) {
    unsigned long long r;
    asm("mov.b64 %0, {%1, %1};" : "=l"(r) : "f"(a));
    return r;
}
__device__ __forceinline__ float2 upk2(unsigned long long v) {
    float a, b;
    asm("mov.b64 {%0, %1}, %2;" : "=f"(a), "=f"(b) : "l"(v));
    return make_float2(a, b);
}
__device__ __forceinline__ unsigned long long fma2(unsigned long long a,
                                                   unsigned long long b,
                                                   unsigned long long c) {
    unsigned long long r;
    asm("fma.rn.f32x2 %0, %1, %2, %3;" : "=l"(r) : "l"(a), "l"(b), "l"(c));
    return r;
}
__device__ __forceinline__ unsigned long long add2(unsigned long long a,
                                                   unsigned long long b) {
    unsigned long long r;
    asm("add.rn.f32x2 %0, %1, %2;" : "=l"(r) : "l"(a), "l"(b));
    return r;
}
__device__ __forceinline__ unsigned long long lds64(const float2* p) {
    return *(const unsigned long long*)p;
}

// Per-batch grid barrier over 64 blocks (atomic counter + 1-thread spin;
// generation-based, graph-replay safe). R7-proven.
__device__ __forceinline__ void batch_barrier(int bb) {
    __syncthreads();
    if (threadIdx.x == 0) {
        __threadfence();
        unsigned gen = g_gen2[bb];
        if (atomicAdd(&g_bar2[bb], 1u) == 63u) {
            g_bar2[bb] = 0;
            __threadfence();
            g_gen2[bb] = gen + 1;
        } else {
            while (g_gen2[bb] == gen) { }
        }
    }
    __syncthreads();
}

// Group-wide (256-thread) reduction of 4 values; two groups (ch=0/1) reduce
// concurrently in disjoint smem slices. All 512 threads must reach the syncs.
__device__ __forceinline__ void red4g(float a, float b, float c, float d,
                                      float* red /*[64]*/, float out[4],
                                      int lane, int gwid, int ch) {
#pragma unroll
    for (int o = 16; o > 0; o >>= 1) {
        a += __shfl_down_sync(0xffffffffu, a, o);
        b += __shfl_down_sync(0xffffffffu, b, o);
        c += __shfl_down_sync(0xffffffffu, c, o);
        d += __shfl_down_sync(0xffffffffu, d, o);
    }
    __syncthreads();
    if (lane == 0) {
        float* r = red + ch * 32;
        r[gwid] = a; r[8 + gwid] = b; r[16 + gwid] = c; r[24 + gwid] = d;
    }
    __syncthreads();
    const float* r = red + ch * 32;
    float t0 = 0.f, t1 = 0.f, t2 = 0.f, t3 = 0.f;
#pragma unroll
    for (int w = 0; w < 8; w++) {
        t0 += r[w]; t1 += r[8 + w]; t2 += r[16 + w]; t3 += r[24 + w];
    }
    out[0] = t0; out[1] = t1; out[2] = t2; out[3] = t3;
}

// ---------------------------------------------------------------------------
// One persistent kernel, 128 blocks x 512 threads (R15 base).
// R16 deltas: GEMV / phase-3 loops at unroll 4 (regs were pinned at the 128
// cap -> likely spills from full-unroll load batching; MLP=8 retained);
// phase-3 weight pairs loaded as one LDS.128. Sort/prefix/search unchanged.
// ---------------------------------------------------------------------------
__global__ void __launch_bounds__(512, 1)
rn_fused(const float* __restrict__ x, const float* __restrict__ y,
         const float* __restrict__ pos, const float* __restrict__ w1,
         const float* __restrict__ w2, const float* __restrict__ b2,
         float* __restrict__ out) {
    __shared__ __align__(16) float2 s_wA[128];    // {Wi_o0[c], Wi_o1[c]}
    __shared__ __align__(16) float2 s_wB[128];    // {Wj_o0[c], Wj_o1[c]}
    __shared__ __align__(16) float2 s_wY[128];    // {Wy_o0[c], Wy_o1[c]}
    __shared__ __align__(16) float2 s_w2p[128];   // {w2_p0[o], w2_p1[o]}
    __shared__ __align__(16) float2 s_eA[1024];   // 4-way partial exchange (A / phase-3)
    __shared__ __align__(16) float2 s_eB[1024];   // 4-way partial exchange (B)
    __shared__ __align__(16) float  s_sx[2][512]; // sort exchange double buffer
    __shared__ __align__(16) float  s_pre[2][257];// inclusive prefix of desc[] per channel
    __shared__ __align__(16) float  s_wt[16];     // warp totals for scan
    __shared__ __align__(16) float  s_red[64];
    __shared__ float s_b2[2];

    const int tid  = threadIdx.x;          // 0..511
    const int lane = tid & 31;
    const int bid  = blockIdx.x;
    const int bb   = bid >> 6;             // batch
    const int o0   = (bid & 63) * 2;       // channel pair
    const int cg   = tid >> 7;             // c-group 0..3 (GEMV phases)
    const int jj   = tid & 127;            // j-slot; thread owns columns jj, jj+128
    const int od   = tid >> 8;             // owner channel 0/1
    const int j    = tid & 255;            // owner column / sort position
    const int gwid = (tid >> 5) & 7;       // warp id within owner group

    // ---- preload packed weights (first use after batch_barrier) ----
    if (tid < 128) {
        const float* w1r = w1 + o0 * 384;
        s_wA[tid]  = make_float2(w1r[tid],       w1r[384 + tid]);
        s_wB[tid]  = make_float2(w1r[128 + tid], w1r[512 + tid]);
        s_wY[tid]  = make_float2(w1r[256 + tid], w1r[640 + tid]);
        const float* w2r = w2 + o0 * 128;
        s_w2p[tid] = make_float2(w2r[tid], w2r[128 + tid]);
    }
    if (tid < 2) s_b2[tid] = b2[o0 + tid];

    // ---- phase 1: group od normalizes row idx = bid*2+od (x with pos, and y) ----
    {
        const int idx = bid * 2 + od;
        const int c   = idx & 127;
        float xv = x[idx * 256 + j] + pos[j * 128 + c];
        float yv = y[idx * 256 + j];
        float r[4];
        red4g(xv, xv * xv, yv, yv * yv, s_red, r, lane, gwid, od);
        const float inv = 1.f / 256.f;
        const float mx = r[0] * inv, my = r[2] * inv;
        const float rx = rsqrtf(r[1] * inv - mx * mx + EPSF);
        const float ry = rsqrtf(r[3] * inv - my * my + EPSF);
        const float xn = fmaxf((xv - mx) * rx, 0.f);
        const float yn = fmaxf((yv - my) * ry, 0.f);
        ((float2*)&g_xy4[bid * 256 + j])[od] = make_float2(xn, yn);
    }

    batch_barrier(bb);

    // ---- phase 2: relate for (bb, o0) and (bb, o0+1) ----
    {
        const float4* __restrict__ xy = g_xy4 + bb * 16384;
        unsigned long long aA0 = 0ull, aB0 = 0ull;   // column jj
        unsigned long long aA1 = 0ull, aB1 = 0ull;   // column jj+128
#pragma unroll 4
        for (int pp = 0; pp < 16; pp++) {
            const int cp = cg * 16 + pp;
            const int c0 = cp * 2;
            const float4 v0 = __ldcg(&xy[cp * 256 + jj]);
            const float4 v1 = __ldcg(&xy[cp * 256 + jj + 128]);
            const unsigned long long wA0 = lds64(&s_wA[c0]);
            const unsigned long long wB0 = lds64(&s_wB[c0]);
            const unsigned long long wY0 = lds64(&s_wY[c0]);
            const unsigned long long wA1 = lds64(&s_wA[c0 + 1]);
            const unsigned long long wB1 = lds64(&s_wB[c0 + 1]);
            const unsigned long long wY1 = lds64(&s_wY[c0 + 1]);
            aA0 = fma2(wA0, dup2(v0.x), aA0);
            aB0 = fma2(wB0, dup2(v0.x), aB0);
            aB0 = fma2(wY0, dup2(v0.y), aB0);
            aA0 = fma2(wA1, dup2(v0.z), aA0);
            aB0 = fma2(wB1, dup2(v0.z), aB0);
            aB0 = fma2(wY1, dup2(v0.w), aB0);
            aA1 = fma2(wA0, dup2(v1.x), aA1);
            aB1 = fma2(wB0, dup2(v1.x), aB1);
            aB1 = fma2(wY0, dup2(v1.y), aB1);
            aA1 = fma2(wA1, dup2(v1.z), aA1);
            aB1 = fma2(wB1, dup2(v1.z), aB1);
            aB1 = fma2(wY1, dup2(v1.w), aB1);
        }
        s_eA[cg * 256 + jj]       = upk2(aA0);
        s_eA[cg * 256 + jj + 128] = upk2(aA1);
        s_eB[cg * 256 + jj]       = upk2(aB0);
        s_eB[cg * 256 + jj + 128] = upk2(aB1);
        __syncthreads();

        // owner (od, j): packed 4-way combine, then select channel od
        unsigned long long pA = add2(add2(lds64(&s_eA[j]),       lds64(&s_eA[256 + j])),
                                     add2(lds64(&s_eA[512 + j]), lds64(&s_eA[768 + j])));
        unsigned long long pB = add2(add2(lds64(&s_eB[j]),       lds64(&s_eB[256 + j])),
                                     add2(lds64(&s_eB[512 + j]), lds64(&s_eB[768 + j])));
        const float2 cA = upk2(pA), cB = upk2(pB);
        const float A = od ? cA.y : cA.x;
        const float B = od ? cB.y : cB.x;

        float r[4];
        red4g(A, A * A, B, B * B, s_red, r, lane, gwid, od);
        const float inv = 1.f / 256.f;
        const float mA = r[0] * inv, mB = r[2] * inv;
        const float rs = rsqrtf((r[1] * inv - mA * mA) + (r[3] * inv - mB * mB) + EPSF);
        float v = (A - mA) * rs;            // a'_j -> to be sorted
        const float t = (B - mB) * rs;      // b'_i

        // ---- bitonic sort DESCENDING over the channel's 256 values ----
        const int sbase = od * 256;
        int buf = 0;
#define SORT_SHFL(K, M) { \
        const float pv = __shfl_xor_sync(0xffffffffu, v, (M)); \
        const bool keepHi = (((j & (K)) == 0) == ((j & (M)) == 0)); \
        v = keepHi ? fmaxf(v, pv) : fminf(v, pv); }
#define SORT_SMEM(K, M) { \
        s_sx[buf][sbase + j] = v; __syncthreads(); \
        const float pv = s_sx[buf][sbase + (j ^ (M))]; \
        const bool keepHi = (((j & (K)) == 0) == ((j & (M)) == 0)); \
        v = keepHi ? fmaxf(v, pv) : fminf(v, pv); \
        buf ^= 1; }

        SORT_SHFL(2, 1)
        SORT_SHFL(4, 2)  SORT_SHFL(4, 1)
        SORT_SHFL(8, 4)  SORT_SHFL(8, 2)  SORT_SHFL(8, 1)
        SORT_SHFL(16, 8) SORT_SHFL(16, 4) SORT_SHFL(16, 2) SORT_SHFL(16, 1)
        SORT_SHFL(32, 16) SORT_SHFL(32, 8) SORT_SHFL(32, 4) SORT_SHFL(32, 2) SORT_SHFL(32, 1)
        SORT_SMEM(64, 32)
        SORT_SHFL(64, 16) SORT_SHFL(64, 8) SORT_SHFL(64, 4) SORT_SHFL(64, 2) SORT_SHFL(64, 1)
        SORT_SMEM(128, 64) SORT_SMEM(128, 32)
        SORT_SHFL(128, 16) SORT_SHFL(128, 8) SORT_SHFL(128, 4) SORT_SHFL(128, 2) SORT_SHFL(128, 1)
        SORT_SMEM(256, 128) SORT_SMEM(256, 64) SORT_SMEM(256, 32)
        SORT_SHFL(256, 16) SORT_SHFL(256, 8) SORT_SHFL(256, 4) SORT_SHFL(256, 2) SORT_SHFL(256, 1)
#undef SORT_SHFL
#undef SORT_SMEM
        // buf == 0 now; buffer 0's pending reads completed before the last
        // smem step's sync -> safe to store the sorted (descending) array.
        s_sx[0][sbase + j] = v;             // desc[j]

        // ---- inclusive scan over desc[] (warp scan + warp totals) ----
        // P[k] = desc[0] + ... + desc[k-1]: direct sum of the relu operands.
        float ps = v;
#pragma unroll
        for (int d = 1; d < 32; d <<= 1) {
            const float n = __shfl_up_sync(0xffffffffu, ps, d);
            if (lane >= d) ps += n;
        }
        if (lane == 31) s_wt[od * 8 + gwid] = ps;
        __syncthreads();
        float off = 0.f;
#pragma unroll
        for (int q = 0; q < 8; q++)
            off += (q < gwid) ? s_wt[od * 8 + q] : 0.f;
        s_pre[od][j + 1] = ps + off;        // P[j+1]
        if (j == 0) s_pre[od][0] = 0.f;
        __syncthreads();

        // ---- binary search: cnt = #{ desc > -t } on non-increasing array ----
        const float u = -t;
        int cnt = 0;
#pragma unroll
        for (int st = 128; st >= 1; st >>= 1) {
            const int nc = cnt + st;
            if (s_sx[0][sbase + nc - 1] > u) cnt = nc;
        }
        // Boundary fix: the descent maxes at 255; admit the 256th element.
        if (cnt == 255 && s_sx[0][sbase + 255] > u) cnt = 256;
        const float s_val = fmaf((float)cnt, t, s_pre[od][cnt]);
        ((float*)&g_s2[bid * 256 + j])[od] = s_val;   // paired store {s_o0, s_o1}
    }

    batch_barrier(bb);

    // ---- phase 3: out[bb, o0+{0,1}, :]; 4-way o-split, 2 j-columns/thread ----
    {
        const float2* __restrict__ sr = g_s2 + bb * 16384;
        unsigned long long ac0 = 0ull, ac1 = 0ull;     // packed (p0, p1)
#pragma unroll 4
        for (int kk = 0; kk < 16; kk++) {
            const int k = cg * 16 + kk;
            const float2 sv0 = __ldcg(&sr[k * 256 + jj]);
            const float2 sv1 = __ldcg(&sr[k * 256 + jj + 128]);
            // one LDS.128 covers both weight pairs {w2p[2k], w2p[2k+1]}
            const float4 wq = *(const float4*)&s_w2p[2 * k];
            unsigned long long w0, w1_;
            asm("mov.b64 %0, {%1, %2};" : "=l"(w0)  : "f"(wq.x), "f"(wq.y));
            asm("mov.b64 %0, {%1, %2};" : "=l"(w1_) : "f"(wq.z), "f"(wq.w));
            ac0 = fma2(w0,  dup2(sv0.x), ac0);
            ac0 = fma2(w1_, dup2(sv0.y), ac0);
            ac1 = fma2(w0,  dup2(sv1.x), ac1);
            ac1 = fma2(w1_, dup2(sv1.y), ac1);
        }
        s_eA[cg * 256 + jj]       = upk2(ac0);
        s_eA[cg * 256 + jj + 128] = upk2(ac1);
        __syncthreads();

        unsigned long long pO = add2(add2(lds64(&s_eA[j]),       lds64(&s_eA[256 + j])),
                                     add2(lds64(&s_eA[512 + j]), lds64(&s_eA[768 + j])));
        const float2 po = upk2(pO);
        const float part = od ? po.y : po.x;
        out[(bb * 128 + o0 + od) * 256 + j] = part + 256.f * s_b2[od];
    }
}

extern "C" void kernel_launch(void* const* d_in, const int* in_sizes, int n_in,
                              void* d_out, int out_size) {
    const float* x   = (const float*)d_in[0];   // (2,128,16,16)
    const float* y   = (const float*)d_in[1];   // (2,128,16,16)
    const float* pos = (const float*)d_in[2];   // (256,128)
    const float* w1  = (const float*)d_in[3];   // (128,384)
    // d_in[4] = b1 — provably unused (cancels in instance-norm centering)
    const float* w2  = (const float*)d_in[5];   // (128,128)
    const float* b2  = (const float*)d_in[6];   // (128,)
    float* out = (float*)d_out;                 // (2,128,16,16)

    rn_fused<<<NB, 512>>>(x, y, pos, w1, w2, b2, out);
}

// round 17
// speedup vs baseline: 1.1404x; 1.1404x over previous
#include <cuda_runtime.h>

#define EPSF 1e-5f
#define NB   128   // 128 blocks < 148 SMs -> co-resident; per-batch barriers over 64 blocks

// Scratch (__device__ globals per allocation-free rule)
__device__ float4 g_xy4[2 * 64 * 256];    // [b][c/2][j] = {x(c0),y(c0),x(c1),y(c1)} normalized
__device__ float2 g_s2 [2 * 64 * 256];    // [b][o/2][j] = {s(o0), s(o1)}
__device__ unsigned g_bar2[2] = {0, 0};
__device__ volatile unsigned g_gen2[2] = {0, 0};

// ---- packed f32x2 helpers ----
__device__ __forceinline__ unsigned long long pk2(float a, float b) {
    unsigned long long r;
    asm("mov.b64 %0, {%1, %2};" : "=l"(r) : "f"(a), "f"(b));
    return r;
}
__device__ __forceinline__ unsigned long long dup2(float a) {
    unsigned long long r;
    asm("mov.b64 %0, {%1, %1};" : "=l"(r) : "f"(a));
    return r;
}
__device__ __forceinline__ float2 upk2(unsigned long long v) {
    float a, b;
    asm("mov.b64 {%0, %1}, %2;" : "=f"(a), "=f"(b) : "l"(v));
    return make_float2(a, b);
}
__device__ __forceinline__ unsigned long long fma2(unsigned long long a,
                                                   unsigned long long b,
                                                   unsigned long long c) {
    unsigned long long r;
    asm("fma.rn.f32x2 %0, %1, %2, %3;" : "=l"(r) : "l"(a), "l"(b), "l"(c));
    return r;
}
__device__ __forceinline__ unsigned long long add2(unsigned long long a,
                                                   unsigned long long b) {
    unsigned long long r;
    asm("add.rn.f32x2 %0, %1, %2;" : "=l"(r) : "l"(a), "l"(b));
    return r;
}
__device__ __forceinline__ unsigned long long lds64(const float2* p) {
    return *(const unsigned long long*)p;
}

// Per-batch grid barrier over 64 blocks (atomic counter + 1-thread spin;
// generation-based, graph-replay safe). R7-proven.
__device__ __forceinline__ void batch_barrier(int bb) {
    __syncthreads();
    if (threadIdx.x == 0) {
        __threadfence();
        unsigned gen = g_gen2[bb];
        if (atomicAdd(&g_bar2[bb], 1u) == 63u) {
            g_bar2[bb] = 0;
            __threadfence();
            g_gen2[bb] = gen + 1;
        } else {
            while (g_gen2[bb] == gen) { }
        }
    }
    __syncthreads();
}

// Group-wide (256-thread) reduction of 4 values; two groups (ch=0/1) reduce
// concurrently in disjoint smem slices. All 512 threads must reach the syncs.
__device__ __forceinline__ void red4g(float a, float b, float c, float d,
                                      float* red /*[64]*/, float out[4],
                                      int lane, int gwid, int ch) {
#pragma unroll
    for (int o = 16; o > 0; o >>= 1) {
        a += __shfl_down_sync(0xffffffffu, a, o);
        b += __shfl_down_sync(0xffffffffu, b, o);
        c += __shfl_down_sync(0xffffffffu, c, o);
        d += __shfl_down_sync(0xffffffffu, d, o);
    }
    __syncthreads();
    if (lane == 0) {
        float* r = red + ch * 32;
        r[gwid] = a; r[8 + gwid] = b; r[16 + gwid] = c; r[24 + gwid] = d;
    }
    __syncthreads();
    const float* r = red + ch * 32;
    float t0 = 0.f, t1 = 0.f, t2 = 0.f, t3 = 0.f;
#pragma unroll
    for (int w = 0; w < 8; w++) {
        t0 += r[w]; t1 += r[8 + w]; t2 += r[16 + w]; t3 += r[24 + w];
    }
    out[0] = t0; out[1] = t1; out[2] = t2; out[3] = t3;
}

// ---------------------------------------------------------------------------
// One persistent kernel, 128 blocks x 512 threads (R15 base, full unroll).
// R17 delta: weight loads vectorized — phase 2 reads the adjacent c0/c0+1
// weight pairs with 3x LDS.128 (was 6x LDS.64); phase 3 reads both o-pair
// weights with 1x LDS.128 (was 2x LDS.64). -64 LDS inst/thread.
// Sort/prefix/boundary-fixed search identical to R15 (rel_err 3e-7 proven).
// ---------------------------------------------------------------------------
__global__ void __launch_bounds__(512, 1)
rn_fused(const float* __restrict__ x, const float* __restrict__ y,
         const float* __restrict__ pos, const float* __restrict__ w1,
         const float* __restrict__ w2, const float* __restrict__ b2,
         float* __restrict__ out) {
    __shared__ __align__(16) float2 s_wA[128];    // {Wi_o0[c], Wi_o1[c]}
    __shared__ __align__(16) float2 s_wB[128];    // {Wj_o0[c], Wj_o1[c]}
    __shared__ __align__(16) float2 s_wY[128];    // {Wy_o0[c], Wy_o1[c]}
    __shared__ __align__(16) float2 s_w2p[128];   // {w2_p0[o], w2_p1[o]}
    __shared__ __align__(16) float2 s_eA[1024];   // 4-way partial exchange (A / phase-3)
    __shared__ __align__(16) float2 s_eB[1024];   // 4-way partial exchange (B)
    __shared__ __align__(16) float  s_sx[2][512]; // sort exchange double buffer
    __shared__ __align__(16) float  s_pre[2][257];// inclusive prefix of desc[] per channel
    __shared__ __align__(16) float  s_wt[16];     // warp totals for scan
    __shared__ __align__(16) float  s_red[64];
    __shared__ float s_b2[2];

    const int tid  = threadIdx.x;          // 0..511
    const int lane = tid & 31;
    const int bid  = blockIdx.x;
    const int bb   = bid >> 6;             // batch
    const int o0   = (bid & 63) * 2;       // channel pair
    const int cg   = tid >> 7;             // c-group 0..3 (GEMV phases)
    const int jj   = tid & 127;            // j-slot; thread owns columns jj, jj+128
    const int od   = tid >> 8;             // owner channel 0/1
    const int j    = tid & 255;            // owner column / sort position
    const int gwid = (tid >> 5) & 7;       // warp id within owner group

    // ---- preload packed weights (first use after batch_barrier) ----
    if (tid < 128) {
        const float* w1r = w1 + o0 * 384;
        s_wA[tid]  = make_float2(w1r[tid],       w1r[384 + tid]);
        s_wB[tid]  = make_float2(w1r[128 + tid], w1r[512 + tid]);
        s_wY[tid]  = make_float2(w1r[256 + tid], w1r[640 + tid]);
        const float* w2r = w2 + o0 * 128;
        s_w2p[tid] = make_float2(w2r[tid], w2r[128 + tid]);
    }
    if (tid < 2) s_b2[tid] = b2[o0 + tid];

    // ---- phase 1: group od normalizes row idx = bid*2+od (x with pos, and y) ----
    {
        const int idx = bid * 2 + od;
        const int c   = idx & 127;
        float xv = x[idx * 256 + j] + pos[j * 128 + c];
        float yv = y[idx * 256 + j];
        float r[4];
        red4g(xv, xv * xv, yv, yv * yv, s_red, r, lane, gwid, od);
        const float inv = 1.f / 256.f;
        const float mx = r[0] * inv, my = r[2] * inv;
        const float rx = rsqrtf(r[1] * inv - mx * mx + EPSF);
        const float ry = rsqrtf(r[3] * inv - my * my + EPSF);
        const float xn = fmaxf((xv - mx) * rx, 0.f);
        const float yn = fmaxf((yv - my) * ry, 0.f);
        ((float2*)&g_xy4[bid * 256 + j])[od] = make_float2(xn, yn);
    }

    batch_barrier(bb);

    // ---- phase 2: relate for (bb, o0) and (bb, o0+1) ----
    {
        const float4* __restrict__ xy = g_xy4 + bb * 16384;
        unsigned long long aA0 = 0ull, aB0 = 0ull;   // column jj
        unsigned long long aA1 = 0ull, aB1 = 0ull;   // column jj+128
#pragma unroll
        for (int pp = 0; pp < 16; pp++) {
            const int cp = cg * 16 + pp;
            const int c0 = cp * 2;
            const float4 v0 = __ldcg(&xy[cp * 256 + jj]);
            const float4 v1 = __ldcg(&xy[cp * 256 + jj + 128]);
            // adjacent c0/c0+1 weight pairs: one LDS.128 per matrix
            const float4 wa = *(const float4*)&s_wA[c0];
            const float4 wb = *(const float4*)&s_wB[c0];
            const float4 wy = *(const float4*)&s_wY[c0];
            const unsigned long long wA0 = pk2(wa.x, wa.y), wA1 = pk2(wa.z, wa.w);
            const unsigned long long wB0 = pk2(wb.x, wb.y), wB1 = pk2(wb.z, wb.w);
            const unsigned long long wY0 = pk2(wy.x, wy.y), wY1 = pk2(wy.z, wy.w);
            aA0 = fma2(wA0, dup2(v0.x), aA0);
            aB0 = fma2(wB0, dup2(v0.x), aB0);
            aB0 = fma2(wY0, dup2(v0.y), aB0);
            aA0 = fma2(wA1, dup2(v0.z), aA0);
            aB0 = fma2(wB1, dup2(v0.z), aB0);
            aB0 = fma2(wY1, dup2(v0.w), aB0);
            aA1 = fma2(wA0, dup2(v1.x), aA1);
            aB1 = fma2(wB0, dup2(v1.x), aB1);
            aB1 = fma2(wY0, dup2(v1.y), aB1);
            aA1 = fma2(wA1, dup2(v1.z), aA1);
            aB1 = fma2(wB1, dup2(v1.z), aB1);
            aB1 = fma2(wY1, dup2(v1.w), aB1);
        }
        s_eA[cg * 256 + jj]       = upk2(aA0);
        s_eA[cg * 256 + jj + 128] = upk2(aA1);
        s_eB[cg * 256 + jj]       = upk2(aB0);
        s_eB[cg * 256 + jj + 128] = upk2(aB1);
        __syncthreads();

        // owner (od, j): packed 4-way combine, then select channel od
        unsigned long long pA = add2(add2(lds64(&s_eA[j]),       lds64(&s_eA[256 + j])),
                                     add2(lds64(&s_eA[512 + j]), lds64(&s_eA[768 + j])));
        unsigned long long pB = add2(add2(lds64(&s_eB[j]),       lds64(&s_eB[256 + j])),
                                     add2(lds64(&s_eB[512 + j]), lds64(&s_eB[768 + j])));
        const float2 cA = upk2(pA), cB = upk2(pB);
        const float A = od ? cA.y : cA.x;
        const float B = od ? cB.y : cB.x;

        float r[4];
        red4g(A, A * A, B, B * B, s_red, r, lane, gwid, od);
        const float inv = 1.f / 256.f;
        const float mA = r[0] * inv, mB = r[2] * inv;
        const float rs = rsqrtf((r[1] * inv - mA * mA) + (r[3] * inv - mB * mB) + EPSF);
        float v = (A - mA) * rs;            // a'_j -> to be sorted
        const float t = (B - mB) * rs;      // b'_i

        // ---- bitonic sort DESCENDING over the channel's 256 values ----
        const int sbase = od * 256;
        int buf = 0;
#define SORT_SHFL(K, M) { \
        const float pv = __shfl_xor_sync(0xffffffffu, v, (M)); \
        const bool keepHi = (((j & (K)) == 0) == ((j & (M)) == 0)); \
        v = keepHi ? fmaxf(v, pv) : fminf(v, pv); }
#define SORT_SMEM(K, M) { \
        s_sx[buf][sbase + j] = v; __syncthreads(); \
        const float pv = s_sx[buf][sbase + (j ^ (M))]; \
        const bool keepHi = (((j & (K)) == 0) == ((j & (M)) == 0)); \
        v = keepHi ? fmaxf(v, pv) : fminf(v, pv); \
        buf ^= 1; }

        SORT_SHFL(2, 1)
        SORT_SHFL(4, 2)  SORT_SHFL(4, 1)
        SORT_SHFL(8, 4)  SORT_SHFL(8, 2)  SORT_SHFL(8, 1)
        SORT_SHFL(16, 8) SORT_SHFL(16, 4) SORT_SHFL(16, 2) SORT_SHFL(16, 1)
        SORT_SHFL(32, 16) SORT_SHFL(32, 8) SORT_SHFL(32, 4) SORT_SHFL(32, 2) SORT_SHFL(32, 1)
        SORT_SMEM(64, 32)
        SORT_SHFL(64, 16) SORT_SHFL(64, 8) SORT_SHFL(64, 4) SORT_SHFL(64, 2) SORT_SHFL(64, 1)
        SORT_SMEM(128, 64) SORT_SMEM(128, 32)
        SORT_SHFL(128, 16) SORT_SHFL(128, 8) SORT_SHFL(128, 4) SORT_SHFL(128, 2) SORT_SHFL(128, 1)
        SORT_SMEM(256, 128) SORT_SMEM(256, 64) SORT_SMEM(256, 32)
        SORT_SHFL(256, 16) SORT_SHFL(256, 8) SORT_SHFL(256, 4) SORT_SHFL(256, 2) SORT_SHFL(256, 1)
#undef SORT_SHFL
#undef SORT_SMEM
        // buf == 0 now; buffer 0's pending reads completed before the last
        // smem step's sync -> safe to store the sorted (descending) array.
        s_sx[0][sbase + j] = v;             // desc[j]

        // ---- inclusive scan over desc[] (warp scan + warp totals) ----
        // P[k] = desc[0] + ... + desc[k-1]: direct sum of the relu operands.
        float ps = v;
#pragma unroll
        for (int d = 1; d < 32; d <<= 1) {
            const float n = __shfl_up_sync(0xffffffffu, ps, d);
            if (lane >= d) ps += n;
        }
        if (lane == 31) s_wt[od * 8 + gwid] = ps;
        __syncthreads();
        float off = 0.f;
#pragma unroll
        for (int q = 0; q < 8; q++)
            off += (q < gwid) ? s_wt[od * 8 + q] : 0.f;
        s_pre[od][j + 1] = ps + off;        // P[j+1]
        if (j == 0) s_pre[od][0] = 0.f;
        __syncthreads();

        // ---- binary search: cnt = #{ desc > -t } on non-increasing array ----
        const float u = -t;
        int cnt = 0;
#pragma unroll
        for (int st = 128; st >= 1; st >>= 1) {
            const int nc = cnt + st;
            if (s_sx[0][sbase + nc - 1] > u) cnt = nc;
        }
        // Boundary fix: the descent maxes at 255; admit the 256th element.
        if (cnt == 255 && s_sx[0][sbase + 255] > u) cnt = 256;
        const float s_val = fmaf((float)cnt, t, s_pre[od][cnt]);
        ((float*)&g_s2[bid * 256 + j])[od] = s_val;   // paired store {s_o0, s_o1}
    }

    batch_barrier(bb);

    // ---- phase 3: out[bb, o0+{0,1}, :]; 4-way o-split, 2 j-columns/thread ----
    {
        const float2* __restrict__ sr = g_s2 + bb * 16384;
        unsigned long long ac0 = 0ull, ac1 = 0ull;     // packed (p0, p1)
#pragma unroll
        for (int kk = 0; kk < 16; kk++) {
            const int k = cg * 16 + kk;
            const float2 sv0 = __ldcg(&sr[k * 256 + jj]);
            const float2 sv1 = __ldcg(&sr[k * 256 + jj + 128]);
            // one LDS.128 covers both weight pairs {w2p[2k], w2p[2k+1]}
            const float4 wq = *(const float4*)&s_w2p[2 * k];
            const unsigned long long w0  = pk2(wq.x, wq.y);
            const unsigned long long w1_ = pk2(wq.z, wq.w);
            ac0 = fma2(w0,  dup2(sv0.x), ac0);
            ac0 = fma2(w1_, dup2(sv0.y), ac0);
            ac1 = fma2(w0,  dup2(sv1.x), ac1);
            ac1 = fma2(w1_, dup2(sv1.y), ac1);
        }
        s_eA[cg * 256 + jj]       = upk2(ac0);
        s_eA[cg * 256 + jj + 128] = upk2(ac1);
        __syncthreads();

        unsigned long long pO = add2(add2(lds64(&s_eA[j]),       lds64(&s_eA[256 + j])),
                                     add2(lds64(&s_eA[512 + j]), lds64(&s_eA[768 + j])));
        const float2 po = upk2(pO);
        const float part = od ? po.y : po.x;
        out[(bb * 128 + o0 + od) * 256 + j] = part + 256.f * s_b2[od];
    }
}

extern "C" void kernel_launch(void* const* d_in, const int* in_sizes, int n_in,
                              void* d_out, int out_size) {
    const float* x   = (const float*)d_in[0];   // (2,128,16,16)
    const float* y   = (const float*)d_in[1];   // (2,128,16,16)
    const float* pos = (const float*)d_in[2];   // (256,128)
    const float* w1  = (const float*)d_in[3];   // (128,384)
    // d_in[4] = b1 — provably unused (cancels in instance-norm centering)
    const float* w2  = (const float*)d_in[5];   // (128,128)
    const float* b2  = (const float*)d_in[6];   // (128,)
    float* out = (float*)d_out;                 // (2,128,16,16)

    rn_fused<<<NB, 512>>>(x, y, pos, w1, w2, b2, out);
}